// round 14
// baseline (speedup 1.0000x reference)
#include <cuda_runtime.h>
#include <cuda_fp16.h>
#include <math.h>
#include <stdint.h>

#define L_SEQ 2048
#define BATCH 2
#define EMB   256
#define NH    8
#define HD    32
#define BH    (NH*BATCH)                 // 16
#define MROWS (L_SEQ*BATCH)              // 4096
#define BR 128
#define BC 64
#define NTILES (L_SEQ/BC)                // 32
#define ATT_SCALE 0.17677669529663687
#define LOG2E    1.4426950408889634
#define SCALE2   ((float)(ATT_SCALE*LOG2E))

typedef unsigned long long u64;

// Scratch (allocation-free rule: __device__ globals)
__device__ __half g_Xh[3*MROWS*EMB];     // converted inputs hi (q,k,v)
__device__ __half g_Xl[3*MROWS*EMB];     // converted inputs lo
__device__ __half g_Wth[4*EMB*EMB];      // transposed weights hi [n][k]
__device__ __half g_Wtl[4*EMB*EMB];      // transposed weights lo
__device__ __half g_Qh[BH*L_SEQ*HD];
__device__ __half g_Ql[BH*L_SEQ*HD];
__device__ __half g_Kh[BH*L_SEQ*HD];     // K: hi only (one-sided split)
__device__ __half g_Vth[BH*HD*L_SEQ];    // V: hi only, transposed [bh][d][l]
__device__ __half g_Oh[MROWS*EMB];       // attention out, row-major hi/lo
__device__ __half g_Ol[MROWS*EMB];

// ---- helpers ----------------------------------------------------------------
__device__ __forceinline__ float ex2(float x) {
    float r; asm("ex2.approx.f32 %0, %1;" : "=f"(r) : "f"(x)); return r;
}
__device__ __forceinline__ uint32_t smem_u32(const void* p) {
    uint32_t a;
    asm("{ .reg .u64 t; cvta.to.shared.u64 t, %1; cvt.u32.u64 %0, t; }" : "=r"(a) : "l"(p));
    return a;
}
__device__ __forceinline__ void ldsm_x2(uint32_t& r0, uint32_t& r1, uint32_t a) {
    asm volatile("ldmatrix.sync.aligned.m8n8.x2.shared.b16 {%0,%1}, [%2];"
                 : "=r"(r0), "=r"(r1) : "r"(a));
}
__device__ __forceinline__ void cpa16(uint32_t dst, const void* src) {
    asm volatile("cp.async.cg.shared.global [%0], [%1], 16;" :: "r"(dst), "l"(src) : "memory");
}
__device__ __forceinline__ void cpa_commit() {
    asm volatile("cp.async.commit_group;" ::: "memory");
}
__device__ __forceinline__ void cpa_wait1() {
    asm volatile("cp.async.wait_group 1;" ::: "memory");
}
__device__ __forceinline__ void cpa_wait0() {
    asm volatile("cp.async.wait_group 0;" ::: "memory");
}
// pack two fp32 into f16x2 (low=p0, high=p1)
__device__ __forceinline__ uint32_t f16x2_of(float p0, float p1) {
    uint32_t r;
    asm("cvt.rn.f16x2.f32 %0, %1, %2;" : "=r"(r) : "f"(p1), "f"(p0));
    return r;
}
// split a pair into fp16 hi frag + fp16 lo (residual) frag
__device__ __forceinline__ void split2(float p0, float p1, uint32_t& hi, uint32_t& lo) {
    hi = f16x2_of(p0, p1);
    __half2 h2 = *reinterpret_cast<__half2*>(&hi);
    float2 hf = __half22float2(h2);
    lo = f16x2_of(p0 - hf.x, p1 - hf.y);
}
// m16n8k16 fp16 mma, row.col, fp32 accumulate in-place
__device__ __forceinline__ void mma16816(float* d, const uint32_t* a, const uint32_t* b) {
    asm volatile(
        "mma.sync.aligned.m16n8k16.row.col.f32.f16.f16.f32 "
        "{%0,%1,%2,%3}, {%4,%5,%6,%7}, {%8,%9}, {%0,%1,%2,%3};"
        : "+f"(d[0]), "+f"(d[1]), "+f"(d[2]), "+f"(d[3])
        : "r"(a[0]), "r"(a[1]), "r"(a[2]), "r"(a[3]), "r"(b[0]), "r"(b[1]));
}

// ---------------------------------------------------------------------------
// Convert inputs: fp32 [MROWS*EMB] -> fp16 hi/lo.  grid (1024, 3), block 256.
// ---------------------------------------------------------------------------
__global__ __launch_bounds__(256) void convert_inputs_kernel(
    const float* __restrict__ q, const float* __restrict__ k, const float* __restrict__ v)
{
    const int which = blockIdx.y;
    const float* src = (which == 0) ? q : (which == 1) ? k : v;
    const int gid = blockIdx.x * 256 + threadIdx.x;
    float4 x = ((const float4*)src)[gid];
    uint32_t h0, l0, h1, l1;
    split2(x.x, x.y, h0, l0);
    split2(x.z, x.w, h1, l1);
    const size_t o = (size_t)which * (MROWS*EMB/2) + (size_t)gid * 2;
    uint2 hv; hv.x = h0; hv.y = h1;
    uint2 lv; lv.x = l0; lv.y = l1;
    ((uint2*)g_Xh)[o >> 1] = hv;
    ((uint2*)g_Xl)[o >> 1] = lv;
}

// ---------------------------------------------------------------------------
// Convert + transpose weights: W[k][n] -> Wt[n][k] fp16 hi/lo. grid (256,4).
// ---------------------------------------------------------------------------
__global__ __launch_bounds__(256) void convert_weights_kernel(
    const float* __restrict__ wq, const float* __restrict__ wk,
    const float* __restrict__ wv, const float* __restrict__ wp)
{
    const int which = blockIdx.y;
    const float* src = (which == 0) ? wq : (which == 1) ? wk : (which == 2) ? wv : wp;
    const int idx = blockIdx.x * 256 + threadIdx.x;
    const int k = idx >> 8, n = idx & 255;
    const float v = src[k*EMB + n];
    __half hb = __float2half_rn(v);
    __half lb = __float2half_rn(v - __half2float(hb));
    const size_t o = (size_t)which*EMB*EMB + (size_t)n*EMB + k;
    g_Wth[o] = hb;
    g_Wtl[o] = lb;
}

// ---------------------------------------------------------------------------
// HMMA GEMM core: BM=128, BN=64, BK=32, 256 threads (8 warps as 4x2),
// double-buffered cp.async, fp16 one/two-sided split.
//   acc = Xh*Wh + Xl*Wh  (+ Xh*Wl if use_wlo)
// ---------------------------------------------------------------------------
#define GX_ROW 80
#define G_OFF_XH 0
#define G_OFF_XL 10240
#define G_OFF_WH 20480
#define G_OFF_WL 25600
#define G_BUF 30720

__device__ __forceinline__ void gemm_core(
    const uint32_t sb, const int t,
    const __half* __restrict__ Xh, const __half* __restrict__ Xl,
    const __half* __restrict__ Wth, const __half* __restrict__ Wtl,
    const int bm, const int bn, const bool use_wlo, float acc[2][4][4])
{
    const int lane = t & 31;
    const int wid  = t >> 5;
    const int wm   = wid >> 1;
    const int wn   = wid & 1;

    auto load_tile = [&](int buf, int kt) {
        const uint32_t base = sb + buf*G_BUF;
        #pragma unroll
        for (int i = 0; i < 2; i++) {
            const int idx = t + i*256;
            const int row = idx >> 2, c = idx & 3;
            const size_t gx = (size_t)(bm + row)*512 + kt*64 + c*16;
            cpa16(base + G_OFF_XH + row*GX_ROW + c*16, (const char*)Xh + gx);
            cpa16(base + G_OFF_XL + row*GX_ROW + c*16, (const char*)Xl + gx);
        }
        {
            const int row = t >> 2, c = t & 3;
            const size_t gw = (size_t)(bn + row)*512 + kt*64 + c*16;
            cpa16(base + G_OFF_WH + row*GX_ROW + c*16, (const char*)Wth + gw);
            if (use_wlo)
                cpa16(base + G_OFF_WL + row*GX_ROW + c*16, (const char*)Wtl + gw);
        }
        cpa_commit();
    };

    load_tile(0, 0);

    for (int kt = 0; kt < 8; kt++) {
        const int buf = kt & 1;
        __syncthreads();
        if (kt + 1 < 8) {
            load_tile(buf ^ 1, kt + 1);
            cpa_wait1();
        } else {
            cpa_wait0();
        }
        __syncthreads();
        const uint32_t base = sb + buf*G_BUF;

        #pragma unroll
        for (int ks = 0; ks < 2; ks++) {
            uint32_t ah[2][4], al[2][4];
            #pragma unroll
            for (int mt = 0; mt < 2; mt++) {
                const uint32_t arow = base + (wm*32 + mt*16 + ((lane>>3)&1)*8 + (lane&7))*GX_ROW
                                    + ks*32;
                ldsm_x2(ah[mt][0], ah[mt][1], arow + G_OFF_XH);
                ldsm_x2(ah[mt][2], ah[mt][3], arow + 16 + G_OFF_XH);
                ldsm_x2(al[mt][0], al[mt][1], arow + G_OFF_XL);
                ldsm_x2(al[mt][2], al[mt][3], arow + 16 + G_OFF_XL);
            }
            uint32_t bhf[4][2], blf[4][2];
            #pragma unroll
            for (int nt = 0; nt < 4; nt++) {
                const uint32_t brow = base + (wn*32 + nt*8 + (lane&7))*GX_ROW
                                    + ((lane>>3)&1)*16 + ks*32;
                ldsm_x2(bhf[nt][0], bhf[nt][1], brow + G_OFF_WH);
                if (use_wlo)
                    ldsm_x2(blf[nt][0], blf[nt][1], brow + G_OFF_WL);
            }
            #pragma unroll
            for (int mt = 0; mt < 2; mt++)
                #pragma unroll
                for (int nt = 0; nt < 4; nt++) {
                    mma16816(acc[mt][nt], ah[mt], bhf[nt]);
                    mma16816(acc[mt][nt], al[mt], bhf[nt]);
                    if (use_wlo)
                        mma16816(acc[mt][nt], ah[mt], blf[nt]);
                }
        }
    }
}

// ---------------------------------------------------------------------------
// Merged QKV GEMM: blockIdx.z selects {Q,K,V}. grid (4, 32, 3).
// Q: hi/lo out.  K: hi only.  V: hi only, transposed, 3-combo math.
// ---------------------------------------------------------------------------
__global__ __launch_bounds__(256) void mma_gemm_qkv_kernel(
    const float* __restrict__ bq, const float* __restrict__ bk, const float* __restrict__ bv)
{
    extern __shared__ __align__(16) char sm[];
    const uint32_t sb = smem_u32(sm);
    const int t  = threadIdx.x;
    const int z  = blockIdx.z;
    const int bm = blockIdx.y * 128;
    const int bn = blockIdx.x * 64;

    const __half* Xh  = g_Xh + (size_t)z*MROWS*EMB;
    const __half* Xl  = g_Xl + (size_t)z*MROWS*EMB;
    const __half* Wth = g_Wth + (size_t)z*EMB*EMB;
    const __half* Wtl = g_Wtl + (size_t)z*EMB*EMB;
    const float* bias = (z == 0) ? bq : (z == 1) ? bk : bv;

    float acc[2][4][4];
    #pragma unroll
    for (int mt = 0; mt < 2; mt++)
        #pragma unroll
        for (int nt = 0; nt < 4; nt++)
            #pragma unroll
            for (int r = 0; r < 4; r++) acc[mt][nt][r] = 0.f;

    gemm_core(sb, t, Xh, Xl, Wth, Wtl, bm, bn, /*use_wlo=*/(z == 2), acc);

    const int lane = t & 31;
    const int wid  = t >> 5;
    const int lr   = lane >> 2;
    const int lc   = lane & 3;
    const int wm   = wid >> 1;
    const int wn   = wid & 1;

    #pragma unroll
    for (int mt = 0; mt < 2; mt++) {
        const int row0 = bm + wm*32 + mt*16 + lr;
        const int row1 = row0 + 8;
        #pragma unroll
        for (int nt = 0; nt < 4; nt++) {
            const int n0 = bn + wn*32 + nt*8 + lc*2;
            const float b0 = bias[n0], b1 = bias[n0+1];
            const float v00 = acc[mt][nt][0] + b0, v01 = acc[mt][nt][1] + b1;
            const float v10 = acc[mt][nt][2] + b0, v11 = acc[mt][nt][3] + b1;
            const int h = n0 >> 5, d = n0 & 31;
            if (z == 0) {            // Q: hi + lo, per-head layout
                #pragma unroll
                for (int rr = 0; rr < 2; rr++) {
                    const int m = rr ? row1 : row0;
                    const int b = m & 1, l = m >> 1;
                    const size_t o = ((size_t)(b*NH + h)*L_SEQ + l)*HD + d;
                    uint32_t hp, lp;
                    split2(rr ? v10 : v00, rr ? v11 : v01, hp, lp);
                    ((uint32_t*)g_Qh)[o >> 1] = hp;
                    ((uint32_t*)g_Ql)[o >> 1] = lp;
                }
            } else if (z == 1) {     // K: hi only, per-head layout
                #pragma unroll
                for (int rr = 0; rr < 2; rr++) {
                    const int m = rr ? row1 : row0;
                    const int b = m & 1, l = m >> 1;
                    const size_t o = ((size_t)(b*NH + h)*L_SEQ + l)*HD + d;
                    ((uint32_t*)g_Kh)[o >> 1] =
                        f16x2_of(rr ? v10 : v00, rr ? v11 : v01);
                }
            } else {                 // V: hi only, transposed layout
                #pragma unroll
                for (int rr = 0; rr < 2; rr++) {
                    const int m = rr ? row1 : row0;
                    const int b = m & 1, l = m >> 1;
                    const size_t o0 = ((size_t)(b*NH + h)*HD + d)*L_SEQ + l;
                    g_Vth[o0]         = __float2half_rn(rr ? v10 : v00);
                    g_Vth[o0 + L_SEQ] = __float2half_rn(rr ? v11 : v01);
                }
            }
        }
    }
}

// ---------------------------------------------------------------------------
// Projection GEMM: fp32 out = (Oh+Ol) @ WpT(hi,+lo) + bp. grid (4, 32).
// ---------------------------------------------------------------------------
__global__ __launch_bounds__(256) void mma_gemm_proj_kernel(
    const float* __restrict__ bias, float* __restrict__ out)
{
    extern __shared__ __align__(16) char sm[];
    const uint32_t sb = smem_u32(sm);
    const int t  = threadIdx.x;
    const int bm = blockIdx.y * 128;
    const int bn = blockIdx.x * 64;

    float acc[2][4][4];
    #pragma unroll
    for (int mt = 0; mt < 2; mt++)
        #pragma unroll
        for (int nt = 0; nt < 4; nt++)
            #pragma unroll
            for (int r = 0; r < 4; r++) acc[mt][nt][r] = 0.f;

    gemm_core(sb, t, g_Oh, g_Ol, g_Wth + 3*EMB*EMB, g_Wtl + 3*EMB*EMB,
              bm, bn, /*use_wlo=*/true, acc);

    const int lane = t & 31;
    const int wid  = t >> 5;
    const int lr   = lane >> 2;
    const int lc   = lane & 3;
    const int wm   = wid >> 1;
    const int wn   = wid & 1;

    #pragma unroll
    for (int mt = 0; mt < 2; mt++) {
        const int row0 = bm + wm*32 + mt*16 + lr;
        const int row1 = row0 + 8;
        #pragma unroll
        for (int nt = 0; nt < 4; nt++) {
            const int n0 = bn + wn*32 + nt*8 + lc*2;
            const float b0 = bias[n0], b1 = bias[n0+1];
            *(float2*)&out[(size_t)row0*EMB + n0] =
                make_float2(acc[mt][nt][0] + b0, acc[mt][nt][1] + b1);
            *(float2*)&out[(size_t)row1*EMB + n0] =
                make_float2(acc[mt][nt][2] + b0, acc[mt][nt][3] + b1);
        }
    }
}

// ---------------------------------------------------------------------------
// Flash attention via fp16 mma.sync + ldmatrix, one-sided splits:
//   S = (Qh + Ql)·Kh^T     (2 combos)
//   O = (Ph + Pl)·Vh       (2 combos)
// fixed-max softmax. grid (L/128, BH), block 128 (4 warps).
// ---------------------------------------------------------------------------
#define KROW 80
#define VROW 144
#define OFF_KH 0
#define OFF_VH 5120
#define BUF_SZ 9728

__global__ __launch_bounds__(128, 2) void flash_mma_kernel()
{
    __shared__ __align__(16) char sm[2][BUF_SZ];
    const uint32_t sb = smem_u32(&sm[0][0]);

    const int t    = threadIdx.x;
    const int w    = t >> 5;
    const int lane = t & 31;
    const int lr   = lane >> 2;
    const int lc   = lane & 3;
    const int bh   = blockIdx.y;
    const int wrow = blockIdx.x * BR + w * 32;

    uint32_t qh[2][2][4], ql[2][2][4];
    #pragma unroll
    for (int mt = 0; mt < 2; mt++)
        #pragma unroll
        for (int s = 0; s < 2; s++)
            #pragma unroll
            for (int r = 0; r < 4; r++) {
                const int row = wrow + mt*16 + ((r & 1) << 3) + lr;
                const int k   = s*16 + ((r >> 1) << 3) + lc*2;
                const size_t idx = (((size_t)bh*L_SEQ + row)*HD + k) >> 1;
                qh[mt][s][r] = ((const uint32_t*)g_Qh)[idx];
                ql[mt][s][r] = ((const uint32_t*)g_Ql)[idx];
            }

    float oacc[2][4][4];
    #pragma unroll
    for (int mt = 0; mt < 2; mt++)
        #pragma unroll
        for (int vn = 0; vn < 4; vn++)
            #pragma unroll
            for (int r = 0; r < 4; r++) oacc[mt][vn][r] = 0.f;
    float lsum[2][2] = {{0.f, 0.f}, {0.f, 0.f}};

    auto load_tile = [&](int buf, int kt) {
        const uint32_t base = sb + buf*BUF_SZ;
        const size_t kgb = ((size_t)bh*L_SEQ + kt*BC)*HD;
        #pragma unroll
        for (int i = 0; i < 2; i++) {
            const int idx = t + i*128;
            const int row = idx >> 2, c = idx & 3;
            cpa16(base + OFF_KH + row*KROW + c*16, (const char*)g_Kh + (kgb + (size_t)row*HD)*2 + c*16);
            const int d = idx >> 3, c2 = idx & 7;
            const size_t vgb = ((size_t)bh*HD + d)*L_SEQ + kt*BC;
            cpa16(base + OFF_VH + d*VROW + c2*16, (const char*)g_Vth + vgb*2 + c2*16);
        }
        cpa_commit();
    };

    load_tile(0, 0);

    for (int kt = 0; kt < NTILES; kt++) {
        const int buf = kt & 1;
        __syncthreads();
        if (kt + 1 < NTILES) {
            load_tile(buf ^ 1, kt + 1);
            cpa_wait1();
        } else {
            cpa_wait0();
        }
        __syncthreads();

        const uint32_t base = sb + buf*BUF_SZ;

        float sacc[2][8][4];
        #pragma unroll
        for (int mt = 0; mt < 2; mt++)
            #pragma unroll
            for (int nt = 0; nt < 8; nt++)
                #pragma unroll
                for (int r = 0; r < 4; r++) sacc[mt][nt][r] = 0.f;

        #pragma unroll
        for (int nt = 0; nt < 8; nt++) {
            const uint32_t krow = base + (nt*8 + (lane & 7))*KROW + ((lane >> 3) & 1)*16;
            uint32_t bhi[2][2];
            #pragma unroll
            for (int s = 0; s < 2; s++)
                ldsm_x2(bhi[s][0], bhi[s][1], krow + s*32 + OFF_KH);
            #pragma unroll
            for (int mt = 0; mt < 2; mt++)
                #pragma unroll
                for (int s = 0; s < 2; s++) {
                    mma16816(sacc[mt][nt], qh[mt][s], bhi[s]);
                    mma16816(sacc[mt][nt], ql[mt][s], bhi[s]);
                }
        }

        #pragma unroll
        for (int mt = 0; mt < 2; mt++)
            #pragma unroll
            for (int nt = 0; nt < 8; nt++) {
                float p0 = ex2(sacc[mt][nt][0] * SCALE2);
                float p1 = ex2(sacc[mt][nt][1] * SCALE2);
                float p2 = ex2(sacc[mt][nt][2] * SCALE2);
                float p3 = ex2(sacc[mt][nt][3] * SCALE2);
                sacc[mt][nt][0] = p0; sacc[mt][nt][1] = p1;
                sacc[mt][nt][2] = p2; sacc[mt][nt][3] = p3;
                lsum[mt][0] += p0 + p1;
                lsum[mt][1] += p2 + p3;
            }

        #pragma unroll
        for (int s = 0; s < 4; s++) {
            uint32_t vbh[4][2];
            #pragma unroll
            for (int vn = 0; vn < 4; vn++) {
                const uint32_t vrow = base + (vn*8 + (lane & 7))*VROW
                                    + ((lane >> 3) & 1)*16 + s*32;
                ldsm_x2(vbh[vn][0], vbh[vn][1], vrow + OFF_VH);
            }
            #pragma unroll
            for (int mt = 0; mt < 2; mt++) {
                uint32_t ahi[4], alo[4];
                split2(sacc[mt][2*s][0],   sacc[mt][2*s][1],   ahi[0], alo[0]);
                split2(sacc[mt][2*s][2],   sacc[mt][2*s][3],   ahi[1], alo[1]);
                split2(sacc[mt][2*s+1][0], sacc[mt][2*s+1][1], ahi[2], alo[2]);
                split2(sacc[mt][2*s+1][2], sacc[mt][2*s+1][3], ahi[3], alo[3]);
                #pragma unroll
                for (int vn = 0; vn < 4; vn++) {
                    mma16816(oacc[mt][vn], ahi, vbh[vn]);
                    mma16816(oacc[mt][vn], alo, vbh[vn]);
                }
            }
        }
    }

    #pragma unroll
    for (int mt = 0; mt < 2; mt++)
        #pragma unroll
        for (int rh = 0; rh < 2; rh++) {
            float v = lsum[mt][rh];
            v += __shfl_xor_sync(0xFFFFFFFFu, v, 1);
            v += __shfl_xor_sync(0xFFFFFFFFu, v, 2);
            lsum[mt][rh] = v;
        }

    // ---- normalize + store O as fp16 hi/lo, row-major [l*BATCH+b][h*HD+d] ----
    const int b = bh >> 3;
    const int h = bh & (NH-1);
    #pragma unroll
    for (int mt = 0; mt < 2; mt++) {
        const float inv0 = 1.f / lsum[mt][0];
        const float inv1 = 1.f / lsum[mt][1];
        const int row0 = wrow + mt*16 + lr;
        const int row1 = row0 + 8;
        #pragma unroll
        for (int vn = 0; vn < 4; vn++) {
            const int col = h*HD + vn*8 + lc*2;
            const size_t o0 = ((size_t)row0*BATCH + b)*EMB + col;
            const size_t o1 = ((size_t)row1*BATCH + b)*EMB + col;
            uint32_t hp, lp;
            split2(oacc[mt][vn][0]*inv0, oacc[mt][vn][1]*inv0, hp, lp);
            ((uint32_t*)g_Oh)[o0 >> 1] = hp;
            ((uint32_t*)g_Ol)[o0 >> 1] = lp;
            split2(oacc[mt][vn][2]*inv1, oacc[mt][vn][3]*inv1, hp, lp);
            ((uint32_t*)g_Oh)[o1 >> 1] = hp;
            ((uint32_t*)g_Ol)[o1 >> 1] = lp;
        }
    }
}

// ---------------------------------------------------------------------------
extern "C" void kernel_launch(void* const* d_in, const int* in_sizes, int n_in,
                              void* d_out, int out_size)
{
    (void)in_sizes; (void)n_in; (void)out_size;
    const float* query = (const float*)d_in[0];
    const float* key_  = (const float*)d_in[1];
    const float* value = (const float*)d_in[2];
    const float* Wq    = (const float*)d_in[3];
    const float* bq    = (const float*)d_in[4];
    const float* Wk    = (const float*)d_in[5];
    const float* bk    = (const float*)d_in[6];
    const float* Wv    = (const float*)d_in[7];
    const float* bv    = (const float*)d_in[8];
    const float* Wp    = (const float*)d_in[9];
    const float* bp    = (const float*)d_in[10];
    float* out = (float*)d_out;

    cudaFuncSetAttribute(mma_gemm_qkv_kernel,  cudaFuncAttributeMaxDynamicSharedMemorySize, 2*G_BUF);
    cudaFuncSetAttribute(mma_gemm_proj_kernel, cudaFuncAttributeMaxDynamicSharedMemorySize, 2*G_BUF);

    convert_inputs_kernel<<<dim3(1024, 3), 256>>>(query, key_, value);
    convert_weights_kernel<<<dim3(256, 4), 256>>>(Wq, Wk, Wv, Wp);

    dim3 ggrid(EMB/64, MROWS/128, 3);   // (4, 32, 3)
    mma_gemm_qkv_kernel<<<ggrid, 256, 2*G_BUF>>>(bq, bk, bv);

    dim3 fgrid(L_SEQ/BR, BH);           // (16, 16)
    flash_mma_kernel<<<fgrid, 128>>>();

    dim3 pgrid(EMB/64, MROWS/128);      // (4, 32)
    mma_gemm_proj_kernel<<<pgrid, 256, 2*G_BUF>>>(bp, out);
}

// round 15
// speedup vs baseline: 1.1226x; 1.1226x over previous
#include <cuda_runtime.h>
#include <cuda_bf16.h>
#include <math.h>
#include <stdint.h>

#define L_SEQ 2048
#define BATCH 2
#define EMB   256
#define NH    8
#define HD    32
#define BH    (NH*BATCH)                 // 16
#define MROWS (L_SEQ*BATCH)              // 4096
#define BR 128
#define BC 64
#define SPLITS 2
#define KV_PER (L_SEQ/SPLITS)            // 1024
#define KTILES (KV_PER/BC)               // 16
#define ATT_SCALE 0.17677669529663687
#define LOG2E    1.4426950408889634
#define SCALE2   ((float)(ATT_SCALE*LOG2E))
#define PART_STRIDE 36

typedef unsigned long long u64;

// Scratch (allocation-free rule: __device__ globals)
__device__ __nv_bfloat16 g_Xh[3*MROWS*EMB];     // converted inputs (q,k,v)
__device__ __nv_bfloat16 g_Xl[3*MROWS*EMB];
__device__ __nv_bfloat16 g_Wth[4*EMB*EMB];      // transposed weights [n][k]
__device__ __nv_bfloat16 g_Wtl[4*EMB*EMB];
__device__ __nv_bfloat16 g_Qh[BH*L_SEQ*HD];
__device__ __nv_bfloat16 g_Ql[BH*L_SEQ*HD];
__device__ __nv_bfloat16 g_Kh[BH*L_SEQ*HD];
__device__ __nv_bfloat16 g_Kl[BH*L_SEQ*HD];
__device__ __nv_bfloat16 g_Vth[BH*HD*L_SEQ];    // transposed [bh][d][l]
__device__ __nv_bfloat16 g_Vtl[BH*HD*L_SEQ];
__device__ __nv_bfloat16 g_Oh[MROWS*EMB];       // attention out, row-major hi/lo
__device__ __nv_bfloat16 g_Ol[MROWS*EMB];
__device__ float g_part[SPLITS*BH*L_SEQ*PART_STRIDE];   // split-KV partials

// ---- helpers ----------------------------------------------------------------
__device__ __forceinline__ float ex2(float x) {
    float r; asm("ex2.approx.f32 %0, %1;" : "=f"(r) : "f"(x)); return r;
}
__device__ __forceinline__ uint32_t smem_u32(const void* p) {
    uint32_t a;
    asm("{ .reg .u64 t; cvta.to.shared.u64 t, %1; cvt.u32.u64 %0, t; }" : "=r"(a) : "l"(p));
    return a;
}
__device__ __forceinline__ void ldsm_x2(uint32_t& r0, uint32_t& r1, uint32_t a) {
    asm volatile("ldmatrix.sync.aligned.m8n8.x2.shared.b16 {%0,%1}, [%2];"
                 : "=r"(r0), "=r"(r1) : "r"(a));
}
__device__ __forceinline__ void cpa16(uint32_t dst, const void* src) {
    asm volatile("cp.async.cg.shared.global [%0], [%1], 16;" :: "r"(dst), "l"(src) : "memory");
}
__device__ __forceinline__ void cpa_commit() {
    asm volatile("cp.async.commit_group;" ::: "memory");
}
__device__ __forceinline__ void cpa_wait1() {
    asm volatile("cp.async.wait_group 1;" ::: "memory");
}
__device__ __forceinline__ void cpa_wait0() {
    asm volatile("cp.async.wait_group 0;" ::: "memory");
}
__device__ __forceinline__ uint32_t bf16x2_of(float p0, float p1) {
    uint32_t r;
    asm("cvt.rn.bf16x2.f32 %0, %1, %2;" : "=r"(r) : "f"(p1), "f"(p0));
    return r;
}
__device__ __forceinline__ void split2(float p0, float p1, uint32_t& hi, uint32_t& lo) {
    hi = bf16x2_of(p0, p1);
    float h0 = __uint_as_float(hi << 16);
    float h1 = __uint_as_float(hi & 0xFFFF0000u);
    lo = bf16x2_of(p0 - h0, p1 - h1);
}
__device__ __forceinline__ void mma16816(float* d, const uint32_t* a, const uint32_t* b) {
    asm volatile(
        "mma.sync.aligned.m16n8k16.row.col.f32.bf16.bf16.f32 "
        "{%0,%1,%2,%3}, {%4,%5,%6,%7}, {%8,%9}, {%0,%1,%2,%3};"
        : "+f"(d[0]), "+f"(d[1]), "+f"(d[2]), "+f"(d[3])
        : "r"(a[0]), "r"(a[1]), "r"(a[2]), "r"(a[3]), "r"(b[0]), "r"(b[1]));
}

// ---------------------------------------------------------------------------
// Convert inputs: fp32 [MROWS*EMB] -> bf16 hi/lo.  grid (1024, 3), block 256.
// ---------------------------------------------------------------------------
__global__ __launch_bounds__(256) void convert_inputs_kernel(
    const float* __restrict__ q, const float* __restrict__ k, const float* __restrict__ v)
{
    const int which = blockIdx.y;
    const float* src = (which == 0) ? q : (which == 1) ? k : v;
    const int gid = blockIdx.x * 256 + threadIdx.x;
    float4 x = ((const float4*)src)[gid];
    uint32_t h0, l0, h1, l1;
    split2(x.x, x.y, h0, l0);
    split2(x.z, x.w, h1, l1);
    const size_t o = (size_t)which * (MROWS*EMB/2) + (size_t)gid * 2;
    uint2 hv; hv.x = h0; hv.y = h1;
    uint2 lv; lv.x = l0; lv.y = l1;
    ((uint2*)g_Xh)[o >> 1] = hv;
    ((uint2*)g_Xl)[o >> 1] = lv;
}

// ---------------------------------------------------------------------------
// Convert + transpose weights: W[k][n] -> Wt[n][k] bf16 hi/lo. grid (256,4).
// ---------------------------------------------------------------------------
__global__ __launch_bounds__(256) void convert_weights_kernel(
    const float* __restrict__ wq, const float* __restrict__ wk,
    const float* __restrict__ wv, const float* __restrict__ wp)
{
    const int which = blockIdx.y;
    const float* src = (which == 0) ? wq : (which == 1) ? wk : (which == 2) ? wv : wp;
    const int idx = blockIdx.x * 256 + threadIdx.x;
    const int k = idx >> 8, n = idx & 255;
    const float v = src[k*EMB + n];
    __nv_bfloat16 hb = __float2bfloat16(v);
    __nv_bfloat16 lb = __float2bfloat16(v - __bfloat162float(hb));
    const size_t o = (size_t)which*EMB*EMB + (size_t)n*EMB + k;
    g_Wth[o] = hb;
    g_Wtl[o] = lb;
}

// ---------------------------------------------------------------------------
// HMMA GEMM core: BM=128, BN=64, BK=32, 256 threads (8 warps as 4x2),
// double-buffered cp.async, bf16 hi/lo split (3 combos).
// ---------------------------------------------------------------------------
#define GX_ROW 80
#define G_OFF_XH 0
#define G_OFF_XL 10240
#define G_OFF_WH 20480
#define G_OFF_WL 25600
#define G_BUF 30720

__device__ __forceinline__ void gemm_core(
    const uint32_t sb, const int t,
    const __nv_bfloat16* __restrict__ Xh, const __nv_bfloat16* __restrict__ Xl,
    const __nv_bfloat16* __restrict__ Wth, const __nv_bfloat16* __restrict__ Wtl,
    const int bm, const int bn, float acc[2][4][4])
{
    const int lane = t & 31;
    const int wid  = t >> 5;
    const int wm   = wid >> 1;
    const int wn   = wid & 1;

    auto load_tile = [&](int buf, int kt) {
        const uint32_t base = sb + buf*G_BUF;
        #pragma unroll
        for (int i = 0; i < 2; i++) {
            const int idx = t + i*256;
            const int row = idx >> 2, c = idx & 3;
            const size_t gx = (size_t)(bm + row)*512 + kt*64 + c*16;
            cpa16(base + G_OFF_XH + row*GX_ROW + c*16, (const char*)Xh + gx);
            cpa16(base + G_OFF_XL + row*GX_ROW + c*16, (const char*)Xl + gx);
        }
        {
            const int row = t >> 2, c = t & 3;
            const size_t gw = (size_t)(bn + row)*512 + kt*64 + c*16;
            cpa16(base + G_OFF_WH + row*GX_ROW + c*16, (const char*)Wth + gw);
            cpa16(base + G_OFF_WL + row*GX_ROW + c*16, (const char*)Wtl + gw);
        }
        cpa_commit();
    };

    load_tile(0, 0);

    for (int kt = 0; kt < 8; kt++) {
        const int buf = kt & 1;
        __syncthreads();
        if (kt + 1 < 8) {
            load_tile(buf ^ 1, kt + 1);
            cpa_wait1();
        } else {
            cpa_wait0();
        }
        __syncthreads();
        const uint32_t base = sb + buf*G_BUF;

        #pragma unroll
        for (int ks = 0; ks < 2; ks++) {
            uint32_t ah[2][4], al[2][4];
            #pragma unroll
            for (int mt = 0; mt < 2; mt++) {
                const uint32_t arow = base + (wm*32 + mt*16 + ((lane>>3)&1)*8 + (lane&7))*GX_ROW
                                    + ks*32;
                ldsm_x2(ah[mt][0], ah[mt][1], arow + G_OFF_XH);
                ldsm_x2(ah[mt][2], ah[mt][3], arow + 16 + G_OFF_XH);
                ldsm_x2(al[mt][0], al[mt][1], arow + G_OFF_XL);
                ldsm_x2(al[mt][2], al[mt][3], arow + 16 + G_OFF_XL);
            }
            uint32_t bhf[4][2], blf[4][2];
            #pragma unroll
            for (int nt = 0; nt < 4; nt++) {
                const uint32_t brow = base + (wn*32 + nt*8 + (lane&7))*GX_ROW
                                    + ((lane>>3)&1)*16 + ks*32;
                ldsm_x2(bhf[nt][0], bhf[nt][1], brow + G_OFF_WH);
                ldsm_x2(blf[nt][0], blf[nt][1], brow + G_OFF_WL);
            }
            #pragma unroll
            for (int mt = 0; mt < 2; mt++)
                #pragma unroll
                for (int nt = 0; nt < 4; nt++) {
                    mma16816(acc[mt][nt], ah[mt], bhf[nt]);
                    mma16816(acc[mt][nt], ah[mt], blf[nt]);
                    mma16816(acc[mt][nt], al[mt], bhf[nt]);
                }
        }
    }
}

// ---------------------------------------------------------------------------
// Merged QKV GEMM: blockIdx.z selects {Q,K,V}. grid (4, 32, 3).
// ---------------------------------------------------------------------------
__global__ __launch_bounds__(256) void mma_gemm_qkv_kernel(
    const float* __restrict__ bq, const float* __restrict__ bk, const float* __restrict__ bv)
{
    extern __shared__ __align__(16) char sm[];
    const uint32_t sb = smem_u32(sm);
    const int t  = threadIdx.x;
    const int z  = blockIdx.z;
    const int bm = blockIdx.y * 128;
    const int bn = blockIdx.x * 64;

    const __nv_bfloat16* Xh  = g_Xh + (size_t)z*MROWS*EMB;
    const __nv_bfloat16* Xl  = g_Xl + (size_t)z*MROWS*EMB;
    const __nv_bfloat16* Wth = g_Wth + (size_t)z*EMB*EMB;
    const __nv_bfloat16* Wtl = g_Wtl + (size_t)z*EMB*EMB;
    const float* bias = (z == 0) ? bq : (z == 1) ? bk : bv;
    __nv_bfloat16* outh = (z == 0) ? g_Qh : (z == 1) ? g_Kh : g_Vth;
    __nv_bfloat16* outl = (z == 0) ? g_Ql : (z == 1) ? g_Kl : g_Vtl;

    float acc[2][4][4];
    #pragma unroll
    for (int mt = 0; mt < 2; mt++)
        #pragma unroll
        for (int nt = 0; nt < 4; nt++)
            #pragma unroll
            for (int r = 0; r < 4; r++) acc[mt][nt][r] = 0.f;

    gemm_core(sb, t, Xh, Xl, Wth, Wtl, bm, bn, acc);

    const int lane = t & 31;
    const int wid  = t >> 5;
    const int lr   = lane >> 2;
    const int lc   = lane & 3;
    const int wm   = wid >> 1;
    const int wn   = wid & 1;

    #pragma unroll
    for (int mt = 0; mt < 2; mt++) {
        const int row0 = bm + wm*32 + mt*16 + lr;
        const int row1 = row0 + 8;
        #pragma unroll
        for (int nt = 0; nt < 4; nt++) {
            const int n0 = bn + wn*32 + nt*8 + lc*2;
            const float b0 = bias[n0], b1 = bias[n0+1];
            const float v00 = acc[mt][nt][0] + b0, v01 = acc[mt][nt][1] + b1;
            const float v10 = acc[mt][nt][2] + b0, v11 = acc[mt][nt][3] + b1;
            const int h = n0 >> 5, d = n0 & 31;
            if (z < 2) {
                #pragma unroll
                for (int rr = 0; rr < 2; rr++) {
                    const int m = rr ? row1 : row0;
                    const int b = m & 1, l = m >> 1;
                    const size_t o = ((size_t)(b*NH + h)*L_SEQ + l)*HD + d;
                    uint32_t hp, lp;
                    split2(rr ? v10 : v00, rr ? v11 : v01, hp, lp);
                    ((uint32_t*)outh)[o >> 1] = hp;
                    ((uint32_t*)outl)[o >> 1] = lp;
                }
            } else {
                #pragma unroll
                for (int rr = 0; rr < 2; rr++) {
                    const int m = rr ? row1 : row0;
                    const int b = m & 1, l = m >> 1;
                    const size_t o0 = ((size_t)(b*NH + h)*HD + d)*L_SEQ + l;
                    const float x0 = rr ? v10 : v00;
                    const float x1 = rr ? v11 : v01;
                    __nv_bfloat16 h0 = __float2bfloat16(x0);
                    __nv_bfloat16 h1 = __float2bfloat16(x1);
                    outh[o0]         = h0;
                    outh[o0 + L_SEQ] = h1;
                    outl[o0]         = __float2bfloat16(x0 - __bfloat162float(h0));
                    outl[o0 + L_SEQ] = __float2bfloat16(x1 - __bfloat162float(h1));
                }
            }
        }
    }
}

// ---------------------------------------------------------------------------
// Projection GEMM: fp32 out = Oh/Ol @ Wp^T + bp. grid (4, 32).
// ---------------------------------------------------------------------------
__global__ __launch_bounds__(256) void mma_gemm_proj_kernel(
    const float* __restrict__ bias, float* __restrict__ out)
{
    extern __shared__ __align__(16) char sm[];
    const uint32_t sb = smem_u32(sm);
    const int t  = threadIdx.x;
    const int bm = blockIdx.y * 128;
    const int bn = blockIdx.x * 64;

    float acc[2][4][4];
    #pragma unroll
    for (int mt = 0; mt < 2; mt++)
        #pragma unroll
        for (int nt = 0; nt < 4; nt++)
            #pragma unroll
            for (int r = 0; r < 4; r++) acc[mt][nt][r] = 0.f;

    gemm_core(sb, t, g_Oh, g_Ol, g_Wth + 3*EMB*EMB, g_Wtl + 3*EMB*EMB, bm, bn, acc);

    const int lane = t & 31;
    const int wid  = t >> 5;
    const int lr   = lane >> 2;
    const int lc   = lane & 3;
    const int wm   = wid >> 1;
    const int wn   = wid & 1;

    #pragma unroll
    for (int mt = 0; mt < 2; mt++) {
        const int row0 = bm + wm*32 + mt*16 + lr;
        const int row1 = row0 + 8;
        #pragma unroll
        for (int nt = 0; nt < 4; nt++) {
            const int n0 = bn + wn*32 + nt*8 + lc*2;
            const float b0 = bias[n0], b1 = bias[n0+1];
            *(float2*)&out[(size_t)row0*EMB + n0] =
                make_float2(acc[mt][nt][0] + b0, acc[mt][nt][1] + b1);
            *(float2*)&out[(size_t)row1*EMB + n0] =
                make_float2(acc[mt][nt][2] + b0, acc[mt][nt][3] + b1);
        }
    }
}

// ---------------------------------------------------------------------------
// Flash attention, split-KV x2, bf16 3-combo, fixed-max softmax.
// Half-tile (32-key) processing: 8 independent QK chains, sacc halved
// to fit 3 CTAs/SM. grid (L/128, BH, SPLITS), block 128.
// ---------------------------------------------------------------------------
#define KROW 80
#define VROW 144
#define OFF_KH 0
#define OFF_KL 5120
#define OFF_VH 10240
#define OFF_VL 14848
#define BUF_SZ 19456

__global__ __launch_bounds__(128, 3) void flash_mma_kernel()
{
    __shared__ __align__(16) char sm[2][BUF_SZ];
    const uint32_t sb = smem_u32(&sm[0][0]);

    const int t    = threadIdx.x;
    const int lane = t & 31;
    const int lr   = lane >> 2;
    const int lc   = lane & 3;
    const int bh   = blockIdx.y;
    const int sp   = blockIdx.z;
    const int wrow = blockIdx.x * BR + (t >> 5) * 32;

    uint32_t qh[2][2][4], ql[2][2][4];
    #pragma unroll
    for (int mt = 0; mt < 2; mt++)
        #pragma unroll
        for (int s = 0; s < 2; s++)
            #pragma unroll
            for (int r = 0; r < 4; r++) {
                const int row = wrow + mt*16 + ((r & 1) << 3) + lr;
                const int k   = s*16 + ((r >> 1) << 3) + lc*2;
                const size_t idx = (((size_t)bh*L_SEQ + row)*HD + k) >> 1;
                qh[mt][s][r] = ((const uint32_t*)g_Qh)[idx];
                ql[mt][s][r] = ((const uint32_t*)g_Ql)[idx];
            }

    float oacc[2][4][4];
    #pragma unroll
    for (int mt = 0; mt < 2; mt++)
        #pragma unroll
        for (int vn = 0; vn < 4; vn++)
            #pragma unroll
            for (int r = 0; r < 4; r++) oacc[mt][vn][r] = 0.f;
    float lsum[2][2] = {{0.f, 0.f}, {0.f, 0.f}};

    auto load_tile = [&](int buf, int kt) {
        const uint32_t base = sb + buf*BUF_SZ;
        const size_t kgb = ((size_t)bh*L_SEQ + sp*KV_PER + kt*BC)*HD;
        #pragma unroll
        for (int i = 0; i < 2; i++) {
            const int idx = t + i*128;
            const int row = idx >> 2, c = idx & 3;
            cpa16(base + OFF_KH + row*KROW + c*16, (const char*)g_Kh + (kgb + (size_t)row*HD)*2 + c*16);
            cpa16(base + OFF_KL + row*KROW + c*16, (const char*)g_Kl + (kgb + (size_t)row*HD)*2 + c*16);
            const int d = idx >> 3, c2 = idx & 7;
            const size_t vgb = ((size_t)bh*HD + d)*L_SEQ + sp*KV_PER + kt*BC;
            cpa16(base + OFF_VH + d*VROW + c2*16, (const char*)g_Vth + vgb*2 + c2*16);
            cpa16(base + OFF_VL + d*VROW + c2*16, (const char*)g_Vtl + vgb*2 + c2*16);
        }
        cpa_commit();
    };

    load_tile(0, 0);

    for (int kt = 0; kt < KTILES; kt++) {
        const int buf = kt & 1;
        __syncthreads();
        if (kt + 1 < KTILES) {
            load_tile(buf ^ 1, kt + 1);
            cpa_wait1();
        } else {
            cpa_wait0();
        }
        __syncthreads();

        const uint32_t base = sb + buf*BUF_SZ;

        // Two 32-key halves: QK (8 indep chains) -> softmax -> PV.
        #pragma unroll
        for (int half = 0; half < 2; half++) {
            float sacc[2][4][4];
            #pragma unroll
            for (int mt = 0; mt < 2; mt++)
                #pragma unroll
                for (int ntl = 0; ntl < 4; ntl++)
                    #pragma unroll
                    for (int r = 0; r < 4; r++) sacc[mt][ntl][r] = 0.f;

            #pragma unroll
            for (int ntl = 0; ntl < 4; ntl++) {
                const int nt = half*4 + ntl;
                const uint32_t krow = base + (nt*8 + (lane & 7))*KROW + ((lane >> 3) & 1)*16;
                uint32_t bhi[2][2], blo[2][2];
                #pragma unroll
                for (int ks = 0; ks < 2; ks++) {
                    ldsm_x2(bhi[ks][0], bhi[ks][1], krow + ks*32 + OFF_KH);
                    ldsm_x2(blo[ks][0], blo[ks][1], krow + ks*32 + OFF_KL);
                }
                #pragma unroll
                for (int mt = 0; mt < 2; mt++)
                    #pragma unroll
                    for (int ks = 0; ks < 2; ks++) {
                        mma16816(sacc[mt][ntl], qh[mt][ks], bhi[ks]);
                        mma16816(sacc[mt][ntl], qh[mt][ks], blo[ks]);
                        mma16816(sacc[mt][ntl], ql[mt][ks], bhi[ks]);
                    }
            }

            // softmax (fixed max), p in place
            #pragma unroll
            for (int mt = 0; mt < 2; mt++)
                #pragma unroll
                for (int ntl = 0; ntl < 4; ntl++) {
                    float p0 = ex2(sacc[mt][ntl][0] * SCALE2);
                    float p1 = ex2(sacc[mt][ntl][1] * SCALE2);
                    float p2 = ex2(sacc[mt][ntl][2] * SCALE2);
                    float p3 = ex2(sacc[mt][ntl][3] * SCALE2);
                    sacc[mt][ntl][0] = p0; sacc[mt][ntl][1] = p1;
                    sacc[mt][ntl][2] = p2; sacc[mt][ntl][3] = p3;
                    lsum[mt][0] += p0 + p1;
                    lsum[mt][1] += p2 + p3;
                }

            // PV for the two 16-key groups in this half
            #pragma unroll
            for (int sl = 0; sl < 2; sl++) {
                const int s = half*2 + sl;
                uint32_t vbh[4][2], vbl[4][2];
                #pragma unroll
                for (int vn = 0; vn < 4; vn++) {
                    const uint32_t vrow = base + (vn*8 + (lane & 7))*VROW
                                        + ((lane >> 3) & 1)*16 + s*32;
                    ldsm_x2(vbh[vn][0], vbh[vn][1], vrow + OFF_VH);
                    ldsm_x2(vbl[vn][0], vbl[vn][1], vrow + OFF_VL);
                }
                #pragma unroll
                for (int mt = 0; mt < 2; mt++) {
                    uint32_t ahi[4], alo[4];
                    split2(sacc[mt][2*sl][0],   sacc[mt][2*sl][1],   ahi[0], alo[0]);
                    split2(sacc[mt][2*sl][2],   sacc[mt][2*sl][3],   ahi[1], alo[1]);
                    split2(sacc[mt][2*sl+1][0], sacc[mt][2*sl+1][1], ahi[2], alo[2]);
                    split2(sacc[mt][2*sl+1][2], sacc[mt][2*sl+1][3], ahi[3], alo[3]);
                    #pragma unroll
                    for (int vn = 0; vn < 4; vn++) {
                        mma16816(oacc[mt][vn], ahi, vbh[vn]);
                        mma16816(oacc[mt][vn], ahi, vbl[vn]);
                        mma16816(oacc[mt][vn], alo, vbh[vn]);
                    }
                }
            }
        }
    }

    #pragma unroll
    for (int mt = 0; mt < 2; mt++)
        #pragma unroll
        for (int rh = 0; rh < 2; rh++) {
            float v = lsum[mt][rh];
            v += __shfl_xor_sync(0xFFFFFFFFu, v, 1);
            v += __shfl_xor_sync(0xFFFFFFFFu, v, 2);
            lsum[mt][rh] = v;
        }

    // ---- store unnormalized partials + lsum ----
    #pragma unroll
    for (int mt = 0; mt < 2; mt++) {
        const int row0 = wrow + mt*16 + lr;
        const int row1 = row0 + 8;
        float* p0 = g_part + ((size_t)(sp*BH + bh)*L_SEQ + row0)*PART_STRIDE;
        float* p1 = g_part + ((size_t)(sp*BH + bh)*L_SEQ + row1)*PART_STRIDE;
        #pragma unroll
        for (int vn = 0; vn < 4; vn++) {
            const int col = vn*8 + lc*2;
            *(float2*)&p0[col] = make_float2(oacc[mt][vn][0], oacc[mt][vn][1]);
            *(float2*)&p1[col] = make_float2(oacc[mt][vn][2], oacc[mt][vn][3]);
        }
        if (lc == 0) {
            p0[HD] = lsum[mt][0];
            p1[HD] = lsum[mt][1];
        }
    }
}

// ---------------------------------------------------------------------------
// Merge split partials -> Oh/Ol bf16 hi/lo, row-major [l*BATCH+b][h*HD+d].
// ---------------------------------------------------------------------------
__global__ __launch_bounds__(256) void merge_kernel()
{
    const int idx = blockIdx.x * 256 + threadIdx.x;   // 0..BH*L_SEQ-1
    if (idx >= BH*L_SEQ) return;
    const int bh = idx >> 11;
    const int r  = idx & (L_SEQ-1);

    float o[HD] = {};
    float l = 0.f;
    #pragma unroll
    for (int s = 0; s < SPLITS; s++) {
        const float* p = g_part + ((size_t)(s*BH + bh)*L_SEQ + r)*PART_STRIDE;
        l += p[HD];
        #pragma unroll
        for (int d4 = 0; d4 < HD/4; d4++) {
            float4 v = ((const float4*)p)[d4];
            o[d4*4+0] += v.x; o[d4*4+1] += v.y;
            o[d4*4+2] += v.z; o[d4*4+3] += v.w;
        }
    }
    const float inv = 1.f / l;
    const int b = bh >> 3;
    const int h = bh & (NH-1);
    const size_t obase = ((size_t)r*BATCH + b)*EMB + h*HD;
    #pragma unroll
    for (int d2 = 0; d2 < HD/2; d2++) {
        uint32_t hp, lp;
        split2(o[2*d2]*inv, o[2*d2+1]*inv, hp, lp);
        ((uint32_t*)g_Oh)[(obase >> 1) + d2] = hp;
        ((uint32_t*)g_Ol)[(obase >> 1) + d2] = lp;
    }
}

// ---------------------------------------------------------------------------
extern "C" void kernel_launch(void* const* d_in, const int* in_sizes, int n_in,
                              void* d_out, int out_size)
{
    (void)in_sizes; (void)n_in; (void)out_size;
    const float* query = (const float*)d_in[0];
    const float* key_  = (const float*)d_in[1];
    const float* value = (const float*)d_in[2];
    const float* Wq    = (const float*)d_in[3];
    const float* bq    = (const float*)d_in[4];
    const float* Wk    = (const float*)d_in[5];
    const float* bk    = (const float*)d_in[6];
    const float* Wv    = (const float*)d_in[7];
    const float* bv    = (const float*)d_in[8];
    const float* Wp    = (const float*)d_in[9];
    const float* bp    = (const float*)d_in[10];
    float* out = (float*)d_out;

    cudaFuncSetAttribute(mma_gemm_qkv_kernel,  cudaFuncAttributeMaxDynamicSharedMemorySize, 2*G_BUF);
    cudaFuncSetAttribute(mma_gemm_proj_kernel, cudaFuncAttributeMaxDynamicSharedMemorySize, 2*G_BUF);

    convert_inputs_kernel<<<dim3(1024, 3), 256>>>(query, key_, value);
    convert_weights_kernel<<<dim3(256, 4), 256>>>(Wq, Wk, Wv, Wp);

    dim3 ggrid(EMB/64, MROWS/128, 3);   // (4, 32, 3)
    mma_gemm_qkv_kernel<<<ggrid, 256, 2*G_BUF>>>(bq, bk, bv);

    dim3 fgrid(L_SEQ/BR, BH, SPLITS);   // (16, 16, 2)
    flash_mma_kernel<<<fgrid, 128>>>();

    merge_kernel<<<(BH*L_SEQ + 255)/256, 256>>>();

    dim3 pgrid(EMB/64, MROWS/128);      // (4, 32)
    mma_gemm_proj_kernel<<<pgrid, 256, 2*G_BUF>>>(bp, out);
}

// round 16
// speedup vs baseline: 1.2403x; 1.1048x over previous
#include <cuda_runtime.h>
#include <cuda_bf16.h>
#include <math.h>
#include <stdint.h>

#define L_SEQ 2048
#define BATCH 2
#define EMB   256
#define NH    8
#define HD    32
#define BH    (NH*BATCH)                 // 16
#define MROWS (L_SEQ*BATCH)              // 4096
#define BR 128
#define BC 64
#define NTILES (L_SEQ/BC)                // 32
#define ATT_SCALE 0.17677669529663687
#define LOG2E    1.4426950408889634
#define SCALE2   ((float)(ATT_SCALE*LOG2E))

typedef unsigned long long u64;

// Scratch (allocation-free rule: __device__ globals)
__device__ __nv_bfloat16 g_Wth[4*EMB*EMB];      // transposed weights [n][k]
__device__ __nv_bfloat16 g_Wtl[4*EMB*EMB];
__device__ __nv_bfloat16 g_Qh[BH*L_SEQ*HD];     // Q pre-scaled by SCALE2
__device__ __nv_bfloat16 g_Ql[BH*L_SEQ*HD];
__device__ __nv_bfloat16 g_Kh[BH*L_SEQ*HD];
__device__ __nv_bfloat16 g_Kl[BH*L_SEQ*HD];
__device__ __nv_bfloat16 g_Vth[BH*HD*L_SEQ];    // transposed [bh][d][l]
__device__ __nv_bfloat16 g_Vtl[BH*HD*L_SEQ];
__device__ __nv_bfloat16 g_Oh[MROWS*EMB];       // attention out, row-major hi/lo
__device__ __nv_bfloat16 g_Ol[MROWS*EMB];

// ---- helpers ----------------------------------------------------------------
__device__ __forceinline__ float ex2(float x) {
    float r; asm("ex2.approx.f32 %0, %1;" : "=f"(r) : "f"(x)); return r;
}
__device__ __forceinline__ uint32_t smem_u32(const void* p) {
    uint32_t a;
    asm("{ .reg .u64 t; cvta.to.shared.u64 t, %1; cvt.u32.u64 %0, t; }" : "=r"(a) : "l"(p));
    return a;
}
__device__ __forceinline__ void ldsm_x2(uint32_t& r0, uint32_t& r1, uint32_t a) {
    asm volatile("ldmatrix.sync.aligned.m8n8.x2.shared.b16 {%0,%1}, [%2];"
                 : "=r"(r0), "=r"(r1) : "r"(a));
}
__device__ __forceinline__ void cpa16(uint32_t dst, const void* src) {
    asm volatile("cp.async.cg.shared.global [%0], [%1], 16;" :: "r"(dst), "l"(src) : "memory");
}
__device__ __forceinline__ void cpa_commit() {
    asm volatile("cp.async.commit_group;" ::: "memory");
}
__device__ __forceinline__ void cpa_wait1() {
    asm volatile("cp.async.wait_group 1;" ::: "memory");
}
__device__ __forceinline__ void cpa_wait0() {
    asm volatile("cp.async.wait_group 0;" ::: "memory");
}
__device__ __forceinline__ uint32_t bf16x2_of(float p0, float p1) {
    uint32_t r;
    asm("cvt.rn.bf16x2.f32 %0, %1, %2;" : "=r"(r) : "f"(p1), "f"(p0));
    return r;
}
__device__ __forceinline__ void split2(float p0, float p1, uint32_t& hi, uint32_t& lo) {
    hi = bf16x2_of(p0, p1);
    float h0 = __uint_as_float(hi << 16);
    float h1 = __uint_as_float(hi & 0xFFFF0000u);
    lo = bf16x2_of(p0 - h0, p1 - h1);
}
__device__ __forceinline__ void mma16816(float* d, const uint32_t* a, const uint32_t* b) {
    asm volatile(
        "mma.sync.aligned.m16n8k16.row.col.f32.bf16.bf16.f32 "
        "{%0,%1,%2,%3}, {%4,%5,%6,%7}, {%8,%9}, {%0,%1,%2,%3};"
        : "+f"(d[0]), "+f"(d[1]), "+f"(d[2]), "+f"(d[3])
        : "r"(a[0]), "r"(a[1]), "r"(a[2]), "r"(a[3]), "r"(b[0]), "r"(b[1]));
}
__device__ __forceinline__ void sts_v2(uint32_t a, uint32_t x, uint32_t y) {
    asm volatile("st.shared.v2.b32 [%0], {%1,%2};" :: "r"(a), "r"(x), "r"(y) : "memory");
}
__device__ __forceinline__ void sts_v4(uint32_t a, uint4 v) {
    asm volatile("st.shared.v4.b32 [%0], {%1,%2,%3,%4};"
                 :: "r"(a), "r"(v.x), "r"(v.y), "r"(v.z), "r"(v.w) : "memory");
}

// ---------------------------------------------------------------------------
// Convert + transpose weights: W[k][n] -> Wt[n][k] bf16 hi/lo. grid (256,4).
// ---------------------------------------------------------------------------
__global__ __launch_bounds__(256) void convert_weights_kernel(
    const float* __restrict__ wq, const float* __restrict__ wk,
    const float* __restrict__ wv, const float* __restrict__ wp)
{
    const int which = blockIdx.y;
    const float* src = (which == 0) ? wq : (which == 1) ? wk : (which == 2) ? wv : wp;
    const int idx = blockIdx.x * 256 + threadIdx.x;
    const int k = idx >> 8, n = idx & 255;
    const float v = src[k*EMB + n];
    __nv_bfloat16 hb = __float2bfloat16(v);
    __nv_bfloat16 lb = __float2bfloat16(v - __bfloat162float(hb));
    const size_t o = (size_t)which*EMB*EMB + (size_t)n*EMB + k;
    g_Wth[o] = hb;
    g_Wtl[o] = lb;
}

// ---------------------------------------------------------------------------
// Shared smem layout constants for both GEMM cores.
// ---------------------------------------------------------------------------
#define GX_ROW 80
#define G_OFF_XH 0
#define G_OFF_XL 10240
#define G_OFF_WH 20480
#define G_OFF_WL 25600
#define G_BUF 30720

// ---------------------------------------------------------------------------
// GEMM core A (fused-convert): X fp32 loaded via register prefetch,
// split hi/lo on smem store. W bf16 hi/lo via LDG prefetch.
// BM=128, BN=64, BK=32, 256 threads (8 warps as 4x2), 3-combo bf16 split.
// ---------------------------------------------------------------------------
__device__ __forceinline__ void gemm_core_f32x(
    const uint32_t sb, const int t,
    const float* __restrict__ X,
    const __nv_bfloat16* __restrict__ Wth, const __nv_bfloat16* __restrict__ Wtl,
    const int bm, const int bn, float acc[2][4][4])
{
    const int lane = t & 31;
    const int wid  = t >> 5;
    const int wm   = wid >> 1;
    const int wn   = wid & 1;

    float4 xr[4];
    uint4 whr, wlr;

    auto prefetch = [&](int kt) {
        #pragma unroll
        for (int i = 0; i < 4; i++) {
            const int idx = t + i*256;
            const int row = idx >> 3, c = idx & 7;
            xr[i] = *(const float4*)&X[(size_t)(bm + row)*EMB + kt*32 + c*4];
        }
        const int row = t >> 2, c = t & 3;
        const size_t gw = (size_t)(bn + row)*EMB + kt*32 + c*8;
        whr = *(const uint4*)&Wth[gw];
        wlr = *(const uint4*)&Wtl[gw];
    };
    auto stores = [&](int buf) {
        const uint32_t base = sb + buf*G_BUF;
        #pragma unroll
        for (int i = 0; i < 4; i++) {
            const int idx = t + i*256;
            const int row = idx >> 3, c = idx & 7;
            uint32_t h0, l0, h1, l1;
            split2(xr[i].x, xr[i].y, h0, l0);
            split2(xr[i].z, xr[i].w, h1, l1);
            const uint32_t off = row*GX_ROW + c*8;
            sts_v2(base + G_OFF_XH + off, h0, h1);
            sts_v2(base + G_OFF_XL + off, l0, l1);
        }
        const int row = t >> 2, c = t & 3;
        const uint32_t woff = row*GX_ROW + c*16;
        sts_v4(base + G_OFF_WH + woff, whr);
        sts_v4(base + G_OFF_WL + woff, wlr);
    };

    prefetch(0);

    for (int kt = 0; kt < 8; kt++) {
        const int buf = kt & 1;
        stores(buf);
        if (kt + 1 < 8) prefetch(kt + 1);
        __syncthreads();

        const uint32_t base = sb + buf*G_BUF;
        #pragma unroll
        for (int ks = 0; ks < 2; ks++) {
            uint32_t ah[2][4], al[2][4];
            #pragma unroll
            for (int mt = 0; mt < 2; mt++) {
                const uint32_t arow = base + (wm*32 + mt*16 + ((lane>>3)&1)*8 + (lane&7))*GX_ROW
                                    + ks*32;
                ldsm_x2(ah[mt][0], ah[mt][1], arow + G_OFF_XH);
                ldsm_x2(ah[mt][2], ah[mt][3], arow + 16 + G_OFF_XH);
                ldsm_x2(al[mt][0], al[mt][1], arow + G_OFF_XL);
                ldsm_x2(al[mt][2], al[mt][3], arow + 16 + G_OFF_XL);
            }
            uint32_t bhf[4][2], blf[4][2];
            #pragma unroll
            for (int nt = 0; nt < 4; nt++) {
                const uint32_t brow = base + (wn*32 + nt*8 + (lane&7))*GX_ROW
                                    + ((lane>>3)&1)*16 + ks*32;
                ldsm_x2(bhf[nt][0], bhf[nt][1], brow + G_OFF_WH);
                ldsm_x2(blf[nt][0], blf[nt][1], brow + G_OFF_WL);
            }
            #pragma unroll
            for (int mt = 0; mt < 2; mt++)
                #pragma unroll
                for (int nt = 0; nt < 4; nt++) {
                    mma16816(acc[mt][nt], ah[mt], bhf[nt]);
                    mma16816(acc[mt][nt], ah[mt], blf[nt]);
                    mma16816(acc[mt][nt], al[mt], bhf[nt]);
                }
        }
        __syncthreads();
    }
}

// ---------------------------------------------------------------------------
// GEMM core B (bf16 inputs, cp.async double-buffer) — used by projection.
// ---------------------------------------------------------------------------
__device__ __forceinline__ void gemm_core(
    const uint32_t sb, const int t,
    const __nv_bfloat16* __restrict__ Xh, const __nv_bfloat16* __restrict__ Xl,
    const __nv_bfloat16* __restrict__ Wth, const __nv_bfloat16* __restrict__ Wtl,
    const int bm, const int bn, float acc[2][4][4])
{
    const int lane = t & 31;
    const int wid  = t >> 5;
    const int wm   = wid >> 1;
    const int wn   = wid & 1;

    auto load_tile = [&](int buf, int kt) {
        const uint32_t base = sb + buf*G_BUF;
        #pragma unroll
        for (int i = 0; i < 2; i++) {
            const int idx = t + i*256;
            const int row = idx >> 2, c = idx & 3;
            const size_t gx = (size_t)(bm + row)*512 + kt*64 + c*16;
            cpa16(base + G_OFF_XH + row*GX_ROW + c*16, (const char*)Xh + gx);
            cpa16(base + G_OFF_XL + row*GX_ROW + c*16, (const char*)Xl + gx);
        }
        {
            const int row = t >> 2, c = t & 3;
            const size_t gw = (size_t)(bn + row)*512 + kt*64 + c*16;
            cpa16(base + G_OFF_WH + row*GX_ROW + c*16, (const char*)Wth + gw);
            cpa16(base + G_OFF_WL + row*GX_ROW + c*16, (const char*)Wtl + gw);
        }
        cpa_commit();
    };

    load_tile(0, 0);

    for (int kt = 0; kt < 8; kt++) {
        const int buf = kt & 1;
        __syncthreads();
        if (kt + 1 < 8) {
            load_tile(buf ^ 1, kt + 1);
            cpa_wait1();
        } else {
            cpa_wait0();
        }
        __syncthreads();
        const uint32_t base = sb + buf*G_BUF;

        #pragma unroll
        for (int ks = 0; ks < 2; ks++) {
            uint32_t ah[2][4], al[2][4];
            #pragma unroll
            for (int mt = 0; mt < 2; mt++) {
                const uint32_t arow = base + (wm*32 + mt*16 + ((lane>>3)&1)*8 + (lane&7))*GX_ROW
                                    + ks*32;
                ldsm_x2(ah[mt][0], ah[mt][1], arow + G_OFF_XH);
                ldsm_x2(ah[mt][2], ah[mt][3], arow + 16 + G_OFF_XH);
                ldsm_x2(al[mt][0], al[mt][1], arow + G_OFF_XL);
                ldsm_x2(al[mt][2], al[mt][3], arow + 16 + G_OFF_XL);
            }
            uint32_t bhf[4][2], blf[4][2];
            #pragma unroll
            for (int nt = 0; nt < 4; nt++) {
                const uint32_t brow = base + (wn*32 + nt*8 + (lane&7))*GX_ROW
                                    + ((lane>>3)&1)*16 + ks*32;
                ldsm_x2(bhf[nt][0], bhf[nt][1], brow + G_OFF_WH);
                ldsm_x2(blf[nt][0], blf[nt][1], brow + G_OFF_WL);
            }
            #pragma unroll
            for (int mt = 0; mt < 2; mt++)
                #pragma unroll
                for (int nt = 0; nt < 4; nt++) {
                    mma16816(acc[mt][nt], ah[mt], bhf[nt]);
                    mma16816(acc[mt][nt], ah[mt], blf[nt]);
                    mma16816(acc[mt][nt], al[mt], bhf[nt]);
                }
        }
    }
}

// ---------------------------------------------------------------------------
// Merged QKV GEMM with fused input conversion. blockIdx.z selects {Q,K,V}.
// grid (4, 32, 3). Q output pre-scaled by SCALE2.
// ---------------------------------------------------------------------------
__global__ __launch_bounds__(256) void mma_gemm_qkv_kernel(
    const float* __restrict__ qx, const float* __restrict__ kx, const float* __restrict__ vx,
    const float* __restrict__ bq, const float* __restrict__ bk, const float* __restrict__ bv)
{
    extern __shared__ __align__(16) char sm[];
    const uint32_t sb = smem_u32(sm);
    const int t  = threadIdx.x;
    const int z  = blockIdx.z;
    const int bm = blockIdx.y * 128;
    const int bn = blockIdx.x * 64;

    const float* X = (z == 0) ? qx : (z == 1) ? kx : vx;
    const __nv_bfloat16* Wth = g_Wth + (size_t)z*EMB*EMB;
    const __nv_bfloat16* Wtl = g_Wtl + (size_t)z*EMB*EMB;
    const float* bias = (z == 0) ? bq : (z == 1) ? bk : bv;

    float acc[2][4][4];
    #pragma unroll
    for (int mt = 0; mt < 2; mt++)
        #pragma unroll
        for (int nt = 0; nt < 4; nt++)
            #pragma unroll
            for (int r = 0; r < 4; r++) acc[mt][nt][r] = 0.f;

    gemm_core_f32x(sb, t, X, Wth, Wtl, bm, bn, acc);

    const int lane = t & 31;
    const int wid  = t >> 5;
    const int lr   = lane >> 2;
    const int lc   = lane & 3;
    const int wm   = wid >> 1;
    const int wn   = wid & 1;

    #pragma unroll
    for (int mt = 0; mt < 2; mt++) {
        const int row0 = bm + wm*32 + mt*16 + lr;
        const int row1 = row0 + 8;
        #pragma unroll
        for (int nt = 0; nt < 4; nt++) {
            const int n0 = bn + wn*32 + nt*8 + lc*2;
            const float b0 = bias[n0], b1 = bias[n0+1];
            float v00 = acc[mt][nt][0] + b0, v01 = acc[mt][nt][1] + b1;
            float v10 = acc[mt][nt][2] + b0, v11 = acc[mt][nt][3] + b1;
            if (z == 0) {   // pre-scale Q so flash softmax is a bare ex2
                v00 *= SCALE2; v01 *= SCALE2; v10 *= SCALE2; v11 *= SCALE2;
            }
            const int h = n0 >> 5, d = n0 & 31;
            if (z < 2) {
                __nv_bfloat16* outh = (z == 0) ? g_Qh : g_Kh;
                __nv_bfloat16* outl = (z == 0) ? g_Ql : g_Kl;
                #pragma unroll
                for (int rr = 0; rr < 2; rr++) {
                    const int m = rr ? row1 : row0;
                    const int b = m & 1, l = m >> 1;
                    const size_t o = ((size_t)(b*NH + h)*L_SEQ + l)*HD + d;
                    uint32_t hp, lp;
                    split2(rr ? v10 : v00, rr ? v11 : v01, hp, lp);
                    ((uint32_t*)outh)[o >> 1] = hp;
                    ((uint32_t*)outl)[o >> 1] = lp;
                }
            } else {
                #pragma unroll
                for (int rr = 0; rr < 2; rr++) {
                    const int m = rr ? row1 : row0;
                    const int b = m & 1, l = m >> 1;
                    const size_t o0 = ((size_t)(b*NH + h)*HD + d)*L_SEQ + l;
                    const float x0 = rr ? v10 : v00;
                    const float x1 = rr ? v11 : v01;
                    __nv_bfloat16 h0 = __float2bfloat16(x0);
                    __nv_bfloat16 h1 = __float2bfloat16(x1);
                    g_Vth[o0]         = h0;
                    g_Vth[o0 + L_SEQ] = h1;
                    g_Vtl[o0]         = __float2bfloat16(x0 - __bfloat162float(h0));
                    g_Vtl[o0 + L_SEQ] = __float2bfloat16(x1 - __bfloat162float(h1));
                }
            }
        }
    }
}

// ---------------------------------------------------------------------------
// Projection GEMM: fp32 out = Oh/Ol @ Wp^T + bp. grid (4, 32).
// ---------------------------------------------------------------------------
__global__ __launch_bounds__(256) void mma_gemm_proj_kernel(
    const float* __restrict__ bias, float* __restrict__ out)
{
    extern __shared__ __align__(16) char sm[];
    const uint32_t sb = smem_u32(sm);
    const int t  = threadIdx.x;
    const int bm = blockIdx.y * 128;
    const int bn = blockIdx.x * 64;

    float acc[2][4][4];
    #pragma unroll
    for (int mt = 0; mt < 2; mt++)
        #pragma unroll
        for (int nt = 0; nt < 4; nt++)
            #pragma unroll
            for (int r = 0; r < 4; r++) acc[mt][nt][r] = 0.f;

    gemm_core(sb, t, g_Oh, g_Ol, g_Wth + 3*EMB*EMB, g_Wtl + 3*EMB*EMB, bm, bn, acc);

    const int lane = t & 31;
    const int wid  = t >> 5;
    const int lr   = lane >> 2;
    const int lc   = lane & 3;
    const int wm   = wid >> 1;
    const int wn   = wid & 1;

    #pragma unroll
    for (int mt = 0; mt < 2; mt++) {
        const int row0 = bm + wm*32 + mt*16 + lr;
        const int row1 = row0 + 8;
        #pragma unroll
        for (int nt = 0; nt < 4; nt++) {
            const int n0 = bn + wn*32 + nt*8 + lc*2;
            const float b0 = bias[n0], b1 = bias[n0+1];
            *(float2*)&out[(size_t)row0*EMB + n0] =
                make_float2(acc[mt][nt][0] + b0, acc[mt][nt][1] + b1);
            *(float2*)&out[(size_t)row1*EMB + n0] =
                make_float2(acc[mt][nt][2] + b0, acc[mt][nt][3] + b1);
        }
    }
}

// ---------------------------------------------------------------------------
// Flash attention via mma.sync + ldmatrix, bf16 3-combo, fixed-max softmax
// (Q pre-scaled -> p = ex2(s)). grid (L/128, BH), block 128 (4 warps).
// ---------------------------------------------------------------------------
#define KROW 80
#define VROW 144
#define OFF_KH 0
#define OFF_KL 5120
#define OFF_VH 10240
#define OFF_VL 14848
#define BUF_SZ 19456

__global__ __launch_bounds__(128, 2) void flash_mma_kernel()
{
    __shared__ __align__(16) char sm[2][BUF_SZ];
    const uint32_t sb = smem_u32(&sm[0][0]);

    const int t    = threadIdx.x;
    const int w    = t >> 5;
    const int lane = t & 31;
    const int lr   = lane >> 2;
    const int lc   = lane & 3;
    const int bh   = blockIdx.y;
    const int wrow = blockIdx.x * BR + w * 32;

    uint32_t qh[2][2][4], ql[2][2][4];
    #pragma unroll
    for (int mt = 0; mt < 2; mt++)
        #pragma unroll
        for (int s = 0; s < 2; s++)
            #pragma unroll
            for (int r = 0; r < 4; r++) {
                const int row = wrow + mt*16 + ((r & 1) << 3) + lr;
                const int k   = s*16 + ((r >> 1) << 3) + lc*2;
                const size_t idx = (((size_t)bh*L_SEQ + row)*HD + k) >> 1;
                qh[mt][s][r] = ((const uint32_t*)g_Qh)[idx];
                ql[mt][s][r] = ((const uint32_t*)g_Ql)[idx];
            }

    float oacc[2][4][4];
    #pragma unroll
    for (int mt = 0; mt < 2; mt++)
        #pragma unroll
        for (int vn = 0; vn < 4; vn++)
            #pragma unroll
            for (int r = 0; r < 4; r++) oacc[mt][vn][r] = 0.f;
    float lsum[2][2] = {{0.f, 0.f}, {0.f, 0.f}};

    auto load_tile = [&](int buf, int kt) {
        const uint32_t base = sb + buf*BUF_SZ;
        const size_t kgb = ((size_t)bh*L_SEQ + kt*BC)*HD;
        #pragma unroll
        for (int i = 0; i < 2; i++) {
            const int idx = t + i*128;
            const int row = idx >> 2, c = idx & 3;
            cpa16(base + OFF_KH + row*KROW + c*16, (const char*)g_Kh + (kgb + (size_t)row*HD)*2 + c*16);
            cpa16(base + OFF_KL + row*KROW + c*16, (const char*)g_Kl + (kgb + (size_t)row*HD)*2 + c*16);
            const int d = idx >> 3, c2 = idx & 7;
            const size_t vgb = ((size_t)bh*HD + d)*L_SEQ + kt*BC;
            cpa16(base + OFF_VH + d*VROW + c2*16, (const char*)g_Vth + vgb*2 + c2*16);
            cpa16(base + OFF_VL + d*VROW + c2*16, (const char*)g_Vtl + vgb*2 + c2*16);
        }
        cpa_commit();
    };

    load_tile(0, 0);

    for (int kt = 0; kt < NTILES; kt++) {
        const int buf = kt & 1;
        __syncthreads();
        if (kt + 1 < NTILES) {
            load_tile(buf ^ 1, kt + 1);
            cpa_wait1();
        } else {
            cpa_wait0();
        }
        __syncthreads();

        const uint32_t base = sb + buf*BUF_SZ;

        float sacc[2][8][4];
        #pragma unroll
        for (int mt = 0; mt < 2; mt++)
            #pragma unroll
            for (int nt = 0; nt < 8; nt++)
                #pragma unroll
                for (int r = 0; r < 4; r++) sacc[mt][nt][r] = 0.f;

        #pragma unroll
        for (int nt = 0; nt < 8; nt++) {
            const uint32_t krow = base + (nt*8 + (lane & 7))*KROW + ((lane >> 3) & 1)*16;
            uint32_t bhi[2][2], blo[2][2];
            #pragma unroll
            for (int s = 0; s < 2; s++) {
                ldsm_x2(bhi[s][0], bhi[s][1], krow + s*32 + OFF_KH);
                ldsm_x2(blo[s][0], blo[s][1], krow + s*32 + OFF_KL);
            }
            #pragma unroll
            for (int mt = 0; mt < 2; mt++)
                #pragma unroll
                for (int s = 0; s < 2; s++) {
                    mma16816(sacc[mt][nt], qh[mt][s], bhi[s]);
                    mma16816(sacc[mt][nt], qh[mt][s], blo[s]);
                    mma16816(sacc[mt][nt], ql[mt][s], bhi[s]);
                }
        }

        #pragma unroll
        for (int mt = 0; mt < 2; mt++)
            #pragma unroll
            for (int nt = 0; nt < 8; nt++) {
                float p0 = ex2(sacc[mt][nt][0]);
                float p1 = ex2(sacc[mt][nt][1]);
                float p2 = ex2(sacc[mt][nt][2]);
                float p3 = ex2(sacc[mt][nt][3]);
                sacc[mt][nt][0] = p0; sacc[mt][nt][1] = p1;
                sacc[mt][nt][2] = p2; sacc[mt][nt][3] = p3;
                lsum[mt][0] += p0 + p1;
                lsum[mt][1] += p2 + p3;
            }

        #pragma unroll
        for (int s = 0; s < 4; s++) {
            uint32_t vbh[4][2], vbl[4][2];
            #pragma unroll
            for (int vn = 0; vn < 4; vn++) {
                const uint32_t vrow = base + (vn*8 + (lane & 7))*VROW
                                    + ((lane >> 3) & 1)*16 + s*32;
                ldsm_x2(vbh[vn][0], vbh[vn][1], vrow + OFF_VH);
                ldsm_x2(vbl[vn][0], vbl[vn][1], vrow + OFF_VL);
            }
            #pragma unroll
            for (int mt = 0; mt < 2; mt++) {
                uint32_t ahi[4], alo[4];
                split2(sacc[mt][2*s][0],   sacc[mt][2*s][1],   ahi[0], alo[0]);
                split2(sacc[mt][2*s][2],   sacc[mt][2*s][3],   ahi[1], alo[1]);
                split2(sacc[mt][2*s+1][0], sacc[mt][2*s+1][1], ahi[2], alo[2]);
                split2(sacc[mt][2*s+1][2], sacc[mt][2*s+1][3], ahi[3], alo[3]);
                #pragma unroll
                for (int vn = 0; vn < 4; vn++) {
                    mma16816(oacc[mt][vn], ahi, vbh[vn]);
                    mma16816(oacc[mt][vn], ahi, vbl[vn]);
                    mma16816(oacc[mt][vn], alo, vbh[vn]);
                }
            }
        }
    }

    #pragma unroll
    for (int mt = 0; mt < 2; mt++)
        #pragma unroll
        for (int rh = 0; rh < 2; rh++) {
            float v = lsum[mt][rh];
            v += __shfl_xor_sync(0xFFFFFFFFu, v, 1);
            v += __shfl_xor_sync(0xFFFFFFFFu, v, 2);
            lsum[mt][rh] = v;
        }

    // ---- normalize + store O as bf16 hi/lo, row-major [l*BATCH+b][h*HD+d] ----
    const int b = bh >> 3;
    const int h = bh & (NH-1);
    #pragma unroll
    for (int mt = 0; mt < 2; mt++) {
        const float inv0 = 1.f / lsum[mt][0];
        const float inv1 = 1.f / lsum[mt][1];
        const int row0 = wrow + mt*16 + lr;
        const int row1 = row0 + 8;
        #pragma unroll
        for (int vn = 0; vn < 4; vn++) {
            const int col = h*HD + vn*8 + lc*2;
            const size_t o0 = ((size_t)row0*BATCH + b)*EMB + col;
            const size_t o1 = ((size_t)row1*BATCH + b)*EMB + col;
            uint32_t hp, lp;
            split2(oacc[mt][vn][0]*inv0, oacc[mt][vn][1]*inv0, hp, lp);
            ((uint32_t*)g_Oh)[o0 >> 1] = hp;
            ((uint32_t*)g_Ol)[o0 >> 1] = lp;
            split2(oacc[mt][vn][2]*inv1, oacc[mt][vn][3]*inv1, hp, lp);
            ((uint32_t*)g_Oh)[o1 >> 1] = hp;
            ((uint32_t*)g_Ol)[o1 >> 1] = lp;
        }
    }
}

// ---------------------------------------------------------------------------
extern "C" void kernel_launch(void* const* d_in, const int* in_sizes, int n_in,
                              void* d_out, int out_size)
{
    (void)in_sizes; (void)n_in; (void)out_size;
    const float* query = (const float*)d_in[0];
    const float* key_  = (const float*)d_in[1];
    const float* value = (const float*)d_in[2];
    const float* Wq    = (const float*)d_in[3];
    const float* bq    = (const float*)d_in[4];
    const float* Wk    = (const float*)d_in[5];
    const float* bk    = (const float*)d_in[6];
    const float* Wv    = (const float*)d_in[7];
    const float* bv    = (const float*)d_in[8];
    const float* Wp    = (const float*)d_in[9];
    const float* bp    = (const float*)d_in[10];
    float* out = (float*)d_out;

    cudaFuncSetAttribute(mma_gemm_qkv_kernel,  cudaFuncAttributeMaxDynamicSharedMemorySize, 2*G_BUF);
    cudaFuncSetAttribute(mma_gemm_proj_kernel, cudaFuncAttributeMaxDynamicSharedMemorySize, 2*G_BUF);

    convert_weights_kernel<<<dim3(256, 4), 256>>>(Wq, Wk, Wv, Wp);

    dim3 ggrid(EMB/64, MROWS/128, 3);   // (4, 32, 3)
    mma_gemm_qkv_kernel<<<ggrid, 256, 2*G_BUF>>>(query, key_, value, bq, bk, bv);

    dim3 fgrid(L_SEQ/BR, BH);           // (16, 16)
    flash_mma_kernel<<<fgrid, 128>>>();

    dim3 pgrid(EMB/64, MROWS/128);      // (4, 32)
    mma_gemm_proj_kernel<<<pgrid, 256, 2*G_BUF>>>(bp, out);
}